// round 11
// baseline (speedup 1.0000x reference)
#include <cuda_runtime.h>
#include <cuda_bf16.h>
#include <cstdint>
#include <cstddef>

// ---------------- problem constants ----------------
constexpr int NUSER = 100000;
constexpr int NITEM = 50000;
constexpr int NN    = 150000;   // total nodes
constexpr int DD    = 128;
constexpr int BB    = 3;
constexpr int LL    = 2;
constexpr int EE    = 1500000;
constexpr float BN_EPS = 1e-5f;
constexpr int SEGS  = BB * NN;                      // 450000 (b,dst) segments
constexpr int SCAN_BLOCKS = (SEGS + 1023) / 1024;   // 440

typedef unsigned long long ull;

// ---------------- device scratch (no allocation allowed) ----------------
__device__ float g_x[(size_t)NN * DD];           // initial node features
__device__ float g_h[(size_t)NN * DD];           // current hidden
__device__ float g_agg[(size_t)NN * DD];         // aggregation scratch
__device__ float g_Q[(size_t)NN * DD];           // attention query
__device__ float g_stack[(size_t)BB * NN * DD];  // per-behavior outputs
__device__ float g_rd[SEGS];                     // 1/max(deg,1)
__device__ float g_logits[(size_t)NN * BB];      // logits, then softmax weights
__device__ float g_colstat[2 * DD];              // BN column sum / sumsq
__device__ float g_bnsc[DD], g_bnsh[DD];         // BN fused scale / shift
__device__ float g_Wc[DD * DD];                  // fuse_W @ refine_W
__device__ float g_bc[DD];                       // fuse_b @ refine_W + refine_b
__device__ int   g_icnt[SEGS];                   // degree per (b,dst)
__device__ int   g_coff[SEGS];                   // CSR offsets
__device__ int   g_ccur[SEGS];                   // fill cursors
__device__ int   g_bsum[SCAN_BLOCKS + 8];
__device__ int   g_bsumoff[SCAN_BLOCKS + 8];
__device__ int   g_csrc[EE];                     // CSR src lists

// ---------------- f32x2 packed-FMA helpers ----------------
#define FFMA2(d, a, b) \
    asm("fma.rn.f32x2 %0, %1, %2, %3;" : "=l"(d) : "l"(a), "l"(b), "l"(d))
#define PACKDUP(d, f) do { unsigned _u = __float_as_uint(f); \
    asm("mov.b64 %0, {%1, %2};" : "=l"(d) : "r"(_u), "r"(_u)); } while (0)
#define UNPK(lo, hi, d) do { unsigned _l, _h; \
    asm("mov.b64 {%0, %1}, %2;" : "=r"(_l), "=r"(_h) : "l"(d)); \
    lo = __uint_as_float(_l); hi = __uint_as_float(_h); } while (0)

// ---------------- small kernels ----------------
__global__ void zero_int_kernel(int4* p, int n4) {
    int i = blockIdx.x * blockDim.x + threadIdx.x;
    int stride = gridDim.x * blockDim.x;
    int4 z = make_int4(0, 0, 0, 0);
    for (; i < n4; i += stride) p[i] = z;
}

__global__ void zero_stats_kernel() {
    if (threadIdx.x < 2 * DD) g_colstat[threadIdx.x] = 0.f;
}

__global__ void count_kernel(const int* __restrict__ ei, const int* __restrict__ et) {
    int e = blockIdx.x * blockDim.x + threadIdx.x;
    if (e >= EE) return;
    atomicAdd(&g_icnt[et[e] * NN + ei[EE + e]], 1);
}

__global__ void scan1_kernel() {
    __shared__ int s[1024];
    int gid = blockIdx.x * 1024 + threadIdx.x;
    int v = (gid < SEGS) ? g_icnt[gid] : 0;
    s[threadIdx.x] = v;
    __syncthreads();
#pragma unroll
    for (int off = 1; off < 1024; off <<= 1) {
        int t = (threadIdx.x >= off) ? s[threadIdx.x - off] : 0;
        __syncthreads();
        s[threadIdx.x] += t;
        __syncthreads();
    }
    if (gid < SEGS) g_coff[gid] = s[threadIdx.x] - v;
    if (threadIdx.x == 1023) g_bsum[blockIdx.x] = s[1023];
}

__global__ void scan2_kernel() {
    __shared__ int s[512];
    int t = threadIdx.x;
    int v = (t < SCAN_BLOCKS) ? g_bsum[t] : 0;
    s[t] = v;
    __syncthreads();
#pragma unroll
    for (int off = 1; off < 512; off <<= 1) {
        int x = (t >= off) ? s[t - off] : 0;
        __syncthreads();
        s[t] += x;
        __syncthreads();
    }
    if (t < SCAN_BLOCKS) g_bsumoff[t] = s[t] - v;
}

__global__ void scan3_kernel() {
    int gid = blockIdx.x * 1024 + threadIdx.x;
    if (gid >= SEGS) return;
    int o = g_coff[gid] + g_bsumoff[gid >> 10];
    g_coff[gid] = o;
    g_ccur[gid] = o;
    g_rd[gid] = 1.0f / fmaxf((float)g_icnt[gid], 1.0f);
}

__global__ void fill_kernel(const int* __restrict__ ei, const int* __restrict__ et) {
    int e = blockIdx.x * blockDim.x + threadIdx.x;
    if (e >= EE) return;
    int pos = atomicAdd(&g_ccur[et[e] * NN + ei[EE + e]], 1);
    g_csrc[pos] = ei[e];
}

// warp-per-dst gather: agg[d] = (1/deg) * sum h[src]
__global__ void gather_kernel(const float* __restrict__ h, float* __restrict__ agg, int b) {
    int w = blockIdx.x * (blockDim.x >> 5) + (threadIdx.x >> 5);
    if (w >= NN) return;
    int lane = threadIdx.x & 31;
    int seg = b * NN + w;
    int lo = g_coff[seg];
    int deg = g_icnt[seg];
    float4 acc = make_float4(0.f, 0.f, 0.f, 0.f);
    const float4* h4 = reinterpret_cast<const float4*>(h);
    for (int j0 = 0; j0 < deg; j0 += 32) {
        int rem = deg - j0;
        int m = rem < 32 ? rem : 32;
        int idx = (lane < m) ? g_csrc[lo + j0 + lane] : 0;
        for (int j = 0; j < m; ++j) {
            int s = __shfl_sync(0xFFFFFFFFu, idx, j);
            float4 v = h4[(size_t)s * 32 + lane];
            acc.x += v.x; acc.y += v.y; acc.z += v.z; acc.w += v.w;
        }
    }
    float r = g_rd[seg];
    acc.x *= r; acc.y *= r; acc.z *= r; acc.w *= r;
    reinterpret_cast<float4*>(agg)[(size_t)w * 32 + lane] = acc;
}

// ---------------- FFMA2 tiled GEMM v2 (128x128 tile, 8x8 per thread) ----------------
// C[M,128] = A@W (+ A2@W2) + bias, optional relu; fused BN colstat / Q-dot logits;
// optional softmax-combined A (soft_stack + soft_w: A row = sum_b w[n,b]*stack_b[n]).
// 256 threads (tx=tid&15, ty=tid>>4); thread tile rows ty*8..+7, cols tx*8..+7.
// smem: AsT[128k][132r] transposed A (broadcast a-reads) + Ws[128k][128c].
constexpr int G2_AST = 0;                         // 128*132*4 = 67584
constexpr int G2_WS  = 67584;                     // 128*128*4 = 65536
constexpr int G2_RED = G2_AST + G2_WS + 65536;    // 133120: sd[128]+sc[512]
constexpr int G2_SMEM = G2_RED + 640 * 4;         // 135680
constexpr int STAGE_STRIDE = 132;                 // stage reuses AsT region

__global__ __launch_bounds__(256) void gemm2_kernel(
    const float* __restrict__ A, const float* __restrict__ W,
    const float* __restrict__ A2, const float* __restrict__ W2,
    const float* __restrict__ bias, float* __restrict__ C,
    int M, int relu, int do_colstat,
    const float* __restrict__ Qdot, float* __restrict__ logits, int bidx,
    const float* __restrict__ soft_stack, const float* __restrict__ soft_w)
{
    extern __shared__ char smem[];
    float* AsT = reinterpret_cast<float*>(smem + G2_AST);
    float* Ws  = reinterpret_cast<float*>(smem + G2_WS);
    int tid = threadIdx.x;
    int tx = tid & 15, ty = tid >> 4;
    int tx8 = tx * 8, ty8 = ty * 8;
    int lane = tid & 31;
    int row0 = blockIdx.x * 128;

    ull acc[8][4];
#pragma unroll
    for (int i = 0; i < 8; i++)
#pragma unroll
        for (int p = 0; p < 4; p++) acc[i][p] = 0ull;

    for (int pass = 0; pass < 2; ++pass) {
        const float* Ap = pass ? A2 : A;
        const float* Wp = pass ? W2 : W;
        bool use_soft = (pass == 0 && soft_stack != nullptr);
        if (Ap == nullptr && !use_soft) break;      // (fixed: soft path has A==nullptr)
        if (pass) __syncthreads();   // finish reading previous tiles

        // load W tile: 128x128 floats, coalesced, conflict-free STS.128
#pragma unroll
        for (int i = 0; i < 16; ++i) {
            int idx = tid + i * 256;
            int k = idx >> 5, c4 = idx & 31;
            float4 v = reinterpret_cast<const float4*>(Wp)[idx];
            *reinterpret_cast<float4*>(&Ws[k * 128 + c4 * 4]) = v;
        }
        // load A tile transposed into AsT[k][r] (scalar STS, broadcast-read later)
#pragma unroll
        for (int i = 0; i < 16; ++i) {
            int idx = tid + i * 256;
            int r = idx >> 5, c4 = idx & 31;
            int gr = row0 + r;
            float4 v = make_float4(0.f, 0.f, 0.f, 0.f);
            if (gr < M) {
                if (use_soft) {
                    float w0 = soft_w[(size_t)gr * 3 + 0];
                    float w1 = soft_w[(size_t)gr * 3 + 1];
                    float w2 = soft_w[(size_t)gr * 3 + 2];
                    size_t fi = (size_t)gr * 32 + c4;
                    float4 s0 = reinterpret_cast<const float4*>(soft_stack)[fi];
                    float4 s1 = reinterpret_cast<const float4*>(soft_stack + (size_t)NN * DD)[fi];
                    float4 s2 = reinterpret_cast<const float4*>(soft_stack + (size_t)2 * NN * DD)[fi];
                    v.x = w0 * s0.x + w1 * s1.x + w2 * s2.x;
                    v.y = w0 * s0.y + w1 * s1.y + w2 * s2.y;
                    v.z = w0 * s0.z + w1 * s1.z + w2 * s2.z;
                    v.w = w0 * s0.w + w1 * s1.w + w2 * s2.w;
                } else {
                    v = reinterpret_cast<const float4*>(Ap)[(size_t)gr * 32 + c4];
                }
            }
            int c = c4 * 4;
            AsT[(c + 0) * 132 + r] = v.x;
            AsT[(c + 1) * 132 + r] = v.y;
            AsT[(c + 2) * 132 + r] = v.z;
            AsT[(c + 3) * 132 + r] = v.w;
        }
        __syncthreads();

#pragma unroll 4
        for (int k = 0; k < DD; ++k) {
            // 8 a-values: 2 broadcast LDS.128 (rows ty8..+7 contiguous in AsT)
            float4 a0 = *reinterpret_cast<const float4*>(&AsT[k * 132 + ty8]);
            float4 a1 = *reinterpret_cast<const float4*>(&AsT[k * 132 + ty8 + 4]);
            ulonglong2 w0 = *reinterpret_cast<const ulonglong2*>(&Ws[k * 128 + tx8]);
            ulonglong2 w1 = *reinterpret_cast<const ulonglong2*>(&Ws[k * 128 + tx8 + 4]);
            ull ad[8];
            PACKDUP(ad[0], a0.x); PACKDUP(ad[1], a0.y);
            PACKDUP(ad[2], a0.z); PACKDUP(ad[3], a0.w);
            PACKDUP(ad[4], a1.x); PACKDUP(ad[5], a1.y);
            PACKDUP(ad[6], a1.z); PACKDUP(ad[7], a1.w);
#pragma unroll
            for (int i = 0; i < 8; ++i) {
                FFMA2(acc[i][0], ad[i], w0.x);
                FFMA2(acc[i][1], ad[i], w0.y);
                FFMA2(acc[i][2], ad[i], w1.x);
                FFMA2(acc[i][3], ad[i], w1.y);
            }
        }
    }
    __syncthreads();   // tiles free; stage reuses AsT region

    // stage accumulators: stage[128][132] fp32
    float* stage = reinterpret_cast<float*>(smem + G2_AST);
    float* sd = reinterpret_cast<float*>(smem + G2_RED);      // 128 floats
    float* sc = sd + 128;                                     // 512 floats
#pragma unroll
    for (int i = 0; i < 8; ++i) {
        float o[8];
        UNPK(o[0], o[1], acc[i][0]);
        UNPK(o[2], o[3], acc[i][1]);
        UNPK(o[4], o[5], acc[i][2]);
        UNPK(o[6], o[7], acc[i][3]);
        *reinterpret_cast<float4*>(&stage[(ty8 + i) * STAGE_STRIDE + tx8]) =
            make_float4(o[0], o[1], o[2], o[3]);
        *reinterpret_cast<float4*>(&stage[(ty8 + i) * STAGE_STRIDE + tx8 + 4]) =
            make_float4(o[4], o[5], o[6], o[7]);
    }
    if (Qdot && tid < 128) sd[tid] = 0.f;
    __syncthreads();

    float s = 0.f, q = 0.f;
    for (int i = tid; i < 16384; i += 256) {
        int r = i >> 7, c = i & 127;
        float v = stage[r * STAGE_STRIDE + c];
        if (bias) v += bias[c];
        if (relu) v = fmaxf(v, 0.f);
        bool valid = (row0 + r) < M;
        if (C != nullptr && valid) C[(size_t)(row0 + r) * 128 + c] = v;
        if (do_colstat && valid) { s += v; q += v * v; }
        if (Qdot != nullptr) {
            float pp = valid ? v * Qdot[(size_t)(row0 + r) * 128 + c] : 0.f;
#pragma unroll
            for (int o = 16; o; o >>= 1) pp += __shfl_xor_sync(0xFFFFFFFFu, pp, o);
            if (lane == 0) atomicAdd(&sd[r], pp);
        }
    }
    if (do_colstat) {
        sc[tid] = s; sc[256 + tid] = q;
        __syncthreads();
        if (tid < 128) {
            atomicAdd(&g_colstat[tid], sc[tid] + sc[tid + 128]);
            atomicAdd(&g_colstat[128 + tid], sc[256 + tid] + sc[256 + tid + 128]);
        }
    }
    if (Qdot != nullptr) {
        __syncthreads();
        if (tid < 128 && row0 + tid < M)
            logits[(size_t)(row0 + tid) * BB + bidx] = sd[tid];
    }
}

// ---------------- BatchNorm finalize / apply ----------------
__global__ void bn_finalize_kernel(const float* __restrict__ gamma, const float* __restrict__ beta) {
    int c = threadIdx.x;
    if (c >= DD) return;
    float mu = g_colstat[c] * (1.0f / NN);
    float var = g_colstat[DD + c] * (1.0f / NN) - mu * mu;
    float sc = gamma[c] * rsqrtf(var + BN_EPS);
    g_bnsc[c] = sc;
    g_bnsh[c] = beta[c] - mu * sc;
}

// mode 0: h = relu(norm(h)) in place.  mode 1: outstack = x + norm(h)
__global__ void bn_apply_kernel(float* __restrict__ h, const float* __restrict__ x,
                                float* __restrict__ outstack, int mode) {
    int idx = blockIdx.x * blockDim.x + threadIdx.x;
    if (idx >= NN * 32) return;
    int c4 = (idx & 31) * 4;
    float4 v = reinterpret_cast<float4*>(h)[idx];
    float4 o;
    o.x = v.x * g_bnsc[c4 + 0] + g_bnsh[c4 + 0];
    o.y = v.y * g_bnsc[c4 + 1] + g_bnsh[c4 + 1];
    o.z = v.z * g_bnsc[c4 + 2] + g_bnsh[c4 + 2];
    o.w = v.w * g_bnsc[c4 + 3] + g_bnsh[c4 + 3];
    if (mode == 0) {
        o.x = fmaxf(o.x, 0.f); o.y = fmaxf(o.y, 0.f);
        o.z = fmaxf(o.z, 0.f); o.w = fmaxf(o.w, 0.f);
        reinterpret_cast<float4*>(h)[idx] = o;
    } else {
        float4 xv = reinterpret_cast<const float4*>(x)[idx];
        o.x += xv.x; o.y += xv.y; o.z += xv.z; o.w += xv.w;
        reinterpret_cast<float4*>(outstack)[idx] = o;
    }
}

// ---------------- softmax weights (in place over logits) ----------------
__global__ void softmax_w_kernel(float* __restrict__ logits) {
    int n = blockIdx.x * blockDim.x + threadIdx.x;
    if (n >= NN) return;
    float l0 = logits[(size_t)n * 3 + 0];
    float l1 = logits[(size_t)n * 3 + 1];
    float l2 = logits[(size_t)n * 3 + 2];
    float m = fmaxf(l0, fmaxf(l1, l2));
    float e0 = __expf(l0 - m), e1 = __expf(l1 - m), e2 = __expf(l2 - m);
    float inv = 1.0f / (e0 + e1 + e2);
    logits[(size_t)n * 3 + 0] = e0 * inv;
    logits[(size_t)n * 3 + 1] = e1 * inv;
    logits[(size_t)n * 3 + 2] = e2 * inv;
}

// bc = fuse_b @ refine_W + refine_b
__global__ void bias_combine_kernel(const float* __restrict__ fuse_b,
                                    const float* __restrict__ refine_W,
                                    const float* __restrict__ refine_b) {
    int c = threadIdx.x;
    if (c >= DD) return;
    float s = refine_b[c];
    for (int k = 0; k < DD; ++k) s += fuse_b[k] * refine_W[k * DD + c];
    g_bc[c] = s;
}

// ---------------- host launch ----------------
static inline int gblk(int m) { return (m + 127) / 128; }

extern "C" void kernel_launch(void* const* d_in, const int* in_sizes, int n_in,
                              void* d_out, int out_size) {
    const int*   ei          = (const int*)d_in[0];
    const int*   et          = (const int*)d_in[1];
    const float* item_feats  = (const float*)d_in[2];
    const float* user_emb    = (const float*)d_in[3];
    const float* user_proj_W = (const float*)d_in[4];
    const float* user_proj_b = (const float*)d_in[5];
    const float* item_proj_W = (const float*)d_in[6];
    const float* item_proj_b = (const float*)d_in[7];
    const float* sage_Wl     = (const float*)d_in[8];
    const float* sage_bl     = (const float*)d_in[9];
    const float* sage_Wr     = (const float*)d_in[10];
    const float* bn_gamma    = (const float*)d_in[11];
    const float* bn_beta     = (const float*)d_in[12];
    const float* query_W     = (const float*)d_in[13];
    const float* query_b     = (const float*)d_in[14];
    const float* key_W       = (const float*)d_in[15];
    const float* key_b       = (const float*)d_in[16];
    const float* fuse_W      = (const float*)d_in[17];
    const float* fuse_b      = (const float*)d_in[18];
    const float* refine_W    = (const float*)d_in[19];
    const float* refine_b    = (const float*)d_in[20];
    float* out = (float*)d_out;
    (void)in_sizes; (void)n_in; (void)out_size;

    float *px, *ph, *pagg, *pQ, *pstack, *plog, *pWc, *pbc;
    int* picnt;
    cudaGetSymbolAddress((void**)&px,     g_x);
    cudaGetSymbolAddress((void**)&ph,     g_h);
    cudaGetSymbolAddress((void**)&pagg,   g_agg);
    cudaGetSymbolAddress((void**)&pQ,     g_Q);
    cudaGetSymbolAddress((void**)&pstack, g_stack);
    cudaGetSymbolAddress((void**)&plog,   g_logits);
    cudaGetSymbolAddress((void**)&pWc,    g_Wc);
    cudaGetSymbolAddress((void**)&pbc,    g_bc);
    cudaGetSymbolAddress((void**)&picnt,  g_icnt);

    cudaFuncSetAttribute(gemm2_kernel, cudaFuncAttributeMaxDynamicSharedMemorySize, G2_SMEM);

    const int NV4 = NN * 32;
    const int APPLY_GRID = (NV4 + 255) / 256;
    const int GATHER_GRID = (NN + 7) / 8;
    const int GB = gblk(NN);                      // 1172

    // ---- edge preprocessing: CSR by (behavior, dst) ----
    zero_int_kernel<<<256, 256>>>((int4*)picnt, SEGS / 4);
    count_kernel<<<(EE + 255) / 256, 256>>>(ei, et);
    scan1_kernel<<<SCAN_BLOCKS, 1024>>>();
    scan2_kernel<<<1, 512>>>();
    scan3_kernel<<<SCAN_BLOCKS, 1024>>>();
    fill_kernel<<<(EE + 255) / 256, 256>>>(ei, et);

    // precombine fuse+refine (no nonlinearity between them)
    gemm2_kernel<<<1, 256, G2_SMEM>>>(fuse_W, refine_W, nullptr, nullptr,
        nullptr, pWc, DD, 0, 0, nullptr, nullptr, 0, nullptr, nullptr);
    bias_combine_kernel<<<1, 128>>>(fuse_b, refine_W, refine_b);

    // initial features x = [user_emb@Wu + bu ; item_feats@Wi + bi]
    gemm2_kernel<<<gblk(NUSER), 256, G2_SMEM>>>(user_emb, user_proj_W, nullptr, nullptr,
        user_proj_b, px, NUSER, 0, 0, nullptr, nullptr, 0, nullptr, nullptr);
    gemm2_kernel<<<gblk(NITEM), 256, G2_SMEM>>>(item_feats, item_proj_W, nullptr, nullptr,
        item_proj_b, px + (size_t)NUSER * DD, NITEM, 0, 0, nullptr, nullptr, 0, nullptr, nullptr);

    for (int b = 0; b < BB; ++b) {
        const float* hin = px;
        for (int l = 0; l < LL; ++l) {
            int bl = b * LL + l;
            gather_kernel<<<GATHER_GRID, 256>>>(hin, pagg, b);
            zero_stats_kernel<<<1, 256>>>();
            // h = agg@Wl + h@Wr + bl  (+ fused BN column stats)
            gemm2_kernel<<<GB, 256, G2_SMEM>>>(pagg, sage_Wl + (size_t)bl * DD * DD,
                hin, sage_Wr + (size_t)bl * DD * DD,
                sage_bl + (size_t)bl * DD, ph, NN, 0, 1, nullptr, nullptr, 0, nullptr, nullptr);
            bn_finalize_kernel<<<1, 128>>>(bn_gamma + (size_t)bl * DD, bn_beta + (size_t)bl * DD);
            if (l < LL - 1) {
                bn_apply_kernel<<<APPLY_GRID, 256>>>(ph, px, nullptr, 0);
            } else {
                bn_apply_kernel<<<APPLY_GRID, 256>>>(ph, px,
                    pstack + (size_t)b * NN * DD, 1);
            }
            hin = ph;
        }
    }

    // attention: Q, then K-GEMMs with fused Q-dot (no K materialization)
    gemm2_kernel<<<GB, 256, G2_SMEM>>>(px, query_W, nullptr, nullptr,
        query_b, pQ, NN, 0, 0, nullptr, nullptr, 0, nullptr, nullptr);
    for (int b = 0; b < BB; ++b) {
        gemm2_kernel<<<GB, 256, G2_SMEM>>>(pstack + (size_t)b * NN * DD,
            key_W + (size_t)b * DD * DD, nullptr, nullptr, key_b + (size_t)b * DD,
            nullptr, NN, 0, 0, pQ, plog, b, nullptr, nullptr);
    }
    // normalize logits -> weights, then final GEMM with fused weighted combine
    softmax_w_kernel<<<(NN + 255) / 256, 256>>>(plog);
    gemm2_kernel<<<GB, 256, G2_SMEM>>>(nullptr, pWc, nullptr, nullptr,
        pbc, out, NN, 1, 0, nullptr, nullptr, 0, pstack, plog);
}

// round 12
// speedup vs baseline: 1.3533x; 1.3533x over previous
#include <cuda_runtime.h>
#include <cuda_bf16.h>
#include <cstdint>
#include <cstddef>

// ---------------- problem constants ----------------
constexpr int NUSER = 100000;
constexpr int NITEM = 50000;
constexpr int NN    = 150000;   // total nodes
constexpr int DD    = 128;
constexpr int BB    = 3;
constexpr int LL    = 2;
constexpr int EE    = 1500000;
constexpr float BN_EPS = 1e-5f;
constexpr int SEGS  = BB * NN;                      // 450000 (b,dst) segments
constexpr int SCAN_BLOCKS = (SEGS + 1023) / 1024;   // 440

typedef unsigned long long ull;

// ---------------- device scratch (no allocation allowed) ----------------
__device__ float g_x[(size_t)NN * DD];           // initial node features
__device__ float g_h[(size_t)NN * DD];           // current hidden
__device__ float g_agg[(size_t)NN * DD];         // aggregation scratch
__device__ float g_Q[(size_t)NN * DD];           // attention query
__device__ float g_stack[(size_t)BB * NN * DD];  // per-behavior outputs
__device__ float g_rd[SEGS];                     // 1/max(deg,1)
__device__ float g_logits[(size_t)NN * BB];      // logits, then softmax weights
__device__ float g_colstat[2 * DD];              // BN column sum / sumsq
__device__ float g_Wc[DD * DD];                  // fuse_W @ refine_W
__device__ float g_bc[DD];                       // fuse_b @ refine_W + refine_b
__device__ int   g_icnt[SEGS];                   // degree per (b,dst)
__device__ int   g_coff[SEGS];                   // CSR offsets
__device__ int   g_ccur[SEGS];                   // fill cursors
__device__ int   g_bsum[SCAN_BLOCKS + 8];
__device__ int   g_bsumoff[SCAN_BLOCKS + 8];
__device__ int   g_csrc[EE];                     // CSR src lists

// ---------------- f32x2 packed-FMA helpers ----------------
#define FFMA2(d, a, b) \
    asm("fma.rn.f32x2 %0, %1, %2, %3;" : "=l"(d) : "l"(a), "l"(b), "l"(d))
#define PACKDUP(d, f) do { unsigned _u = __float_as_uint(f); \
    asm("mov.b64 %0, {%1, %2};" : "=l"(d) : "r"(_u), "r"(_u)); } while (0)
#define UNPK(lo, hi, d) do { unsigned _l, _h; \
    asm("mov.b64 {%0, %1}, %2;" : "=r"(_l), "=r"(_h) : "l"(d)); \
    lo = __uint_as_float(_l); hi = __uint_as_float(_h); } while (0)

// ---------------- small kernels ----------------
__global__ void zero_int_kernel(int4* p, int n4) {
    int i = blockIdx.x * blockDim.x + threadIdx.x;
    int stride = gridDim.x * blockDim.x;
    int4 z = make_int4(0, 0, 0, 0);
    for (; i < n4; i += stride) p[i] = z;
}

__global__ void count_kernel(const int* __restrict__ ei, const int* __restrict__ et) {
    int e = blockIdx.x * blockDim.x + threadIdx.x;
    if (e >= EE) return;
    atomicAdd(&g_icnt[et[e] * NN + ei[EE + e]], 1);
}

__global__ void scan1_kernel() {
    __shared__ int s[1024];
    int gid = blockIdx.x * 1024 + threadIdx.x;
    int v = (gid < SEGS) ? g_icnt[gid] : 0;
    s[threadIdx.x] = v;
    __syncthreads();
#pragma unroll
    for (int off = 1; off < 1024; off <<= 1) {
        int t = (threadIdx.x >= off) ? s[threadIdx.x - off] : 0;
        __syncthreads();
        s[threadIdx.x] += t;
        __syncthreads();
    }
    if (gid < SEGS) g_coff[gid] = s[threadIdx.x] - v;
    if (threadIdx.x == 1023) g_bsum[blockIdx.x] = s[1023];
}

__global__ void scan2_kernel() {
    __shared__ int s[512];
    int t = threadIdx.x;
    int v = (t < SCAN_BLOCKS) ? g_bsum[t] : 0;
    s[t] = v;
    __syncthreads();
#pragma unroll
    for (int off = 1; off < 512; off <<= 1) {
        int x = (t >= off) ? s[t - off] : 0;
        __syncthreads();
        s[t] += x;
        __syncthreads();
    }
    if (t < SCAN_BLOCKS) g_bsumoff[t] = s[t] - v;
}

__global__ void scan3_kernel() {
    int gid = blockIdx.x * 1024 + threadIdx.x;
    if (gid >= SEGS) return;
    int o = g_coff[gid] + g_bsumoff[gid >> 10];
    g_coff[gid] = o;
    g_ccur[gid] = o;
    g_rd[gid] = 1.0f / fmaxf((float)g_icnt[gid], 1.0f);
}

__global__ void fill_kernel(const int* __restrict__ ei, const int* __restrict__ et) {
    int e = blockIdx.x * blockDim.x + threadIdx.x;
    if (e >= EE) return;
    int pos = atomicAdd(&g_ccur[et[e] * NN + ei[EE + e]], 1);
    g_csrc[pos] = ei[e];
}

// warp-per-dst gather: agg[d] = (1/deg) * sum h[src]; block 0 zeroes colstat
__global__ void gather_kernel(const float* __restrict__ h, float* __restrict__ agg, int b) {
    if (blockIdx.x == 0 && threadIdx.x < 2 * DD) g_colstat[threadIdx.x] = 0.f;
    int w = blockIdx.x * (blockDim.x >> 5) + (threadIdx.x >> 5);
    if (w >= NN) return;
    int lane = threadIdx.x & 31;
    int seg = b * NN + w;
    int lo = g_coff[seg];
    int deg = g_icnt[seg];
    float4 acc = make_float4(0.f, 0.f, 0.f, 0.f);
    const float4* h4 = reinterpret_cast<const float4*>(h);
    for (int j0 = 0; j0 < deg; j0 += 32) {
        int rem = deg - j0;
        int m = rem < 32 ? rem : 32;
        int idx = (lane < m) ? g_csrc[lo + j0 + lane] : 0;
        for (int j = 0; j < m; ++j) {
            int s = __shfl_sync(0xFFFFFFFFu, idx, j);
            float4 v = h4[(size_t)s * 32 + lane];
            acc.x += v.x; acc.y += v.y; acc.z += v.z; acc.w += v.w;
        }
    }
    float r = g_rd[seg];
    acc.x *= r; acc.y *= r; acc.z *= r; acc.w *= r;
    reinterpret_cast<float4*>(agg)[(size_t)w * 32 + lane] = acc;
}

// ---------------- FFMA2 tiled GEMM (64-row tile, proven R5 config) ----------------
// C[M,128] = A@W (+ A2@W2) + bias, optional relu; fused BN colstat / Q-dot logits;
// optional softmax-combined A (soft_stack + soft_w).
// 256 threads (tx=tid&15, ty=tid>>4); thread = 4 rows x 8 cols (tx*4..+3, 64+tx*4..+3).
constexpr int GEMM_SMEM = (128 * 64 + 128 * 128) * 4;   // 96 KB -> 2 CTAs/SM

__global__ __launch_bounds__(256) void gemm_kernel(
    const float* __restrict__ A, const float* __restrict__ W,
    const float* __restrict__ A2, const float* __restrict__ W2,
    const float* __restrict__ bias, float* __restrict__ C,
    int M, int relu, int do_colstat,
    const float* __restrict__ Qdot, float* __restrict__ logits, int bidx,
    const float* __restrict__ soft_stack, const float* __restrict__ soft_w)
{
    extern __shared__ float sm[];
    float* AsT = sm;                 // [128][64] k-major
    float* Ws  = sm + 128 * 64;      // [128][128]
    int tid = threadIdx.x;
    int tx = tid & 15, ty = tid >> 4;
    int row0 = blockIdx.x * 64;

    ull acc[4][4];
#pragma unroll
    for (int i = 0; i < 4; i++)
#pragma unroll
        for (int p = 0; p < 4; p++) acc[i][p] = 0ull;

    for (int pass = 0; pass < 2; ++pass) {
        const float* Ap = pass ? A2 : A;
        const float* Wp = pass ? W2 : W;
        bool use_soft = (pass == 0 && soft_stack != nullptr);
        if (Ap == nullptr && !use_soft) break;
        if (pass) __syncthreads();   // finish reading previous tiles

        // load W tile (coalesced, conflict-free STS.128)
#pragma unroll
        for (int i = 0; i < 16; ++i) {
            int idx = tid + i * 256;
            reinterpret_cast<float4*>(Ws)[idx] = reinterpret_cast<const float4*>(Wp)[idx];
        }
        // load A tile transposed
#pragma unroll
        for (int i = 0; i < 8; ++i) {
            int idx = tid + i * 256;
            int r = idx & 63, c4 = idx >> 6;     // c4 in 0..31
            int gr = row0 + r;
            float4 v = make_float4(0.f, 0.f, 0.f, 0.f);
            if (gr < M) {
                if (use_soft) {
                    float w0 = soft_w[(size_t)gr * 3 + 0];
                    float w1 = soft_w[(size_t)gr * 3 + 1];
                    float w2 = soft_w[(size_t)gr * 3 + 2];
                    size_t fi = (size_t)gr * 32 + c4;
                    float4 s0 = reinterpret_cast<const float4*>(soft_stack)[fi];
                    float4 s1 = reinterpret_cast<const float4*>(soft_stack + (size_t)NN * DD)[fi];
                    float4 s2 = reinterpret_cast<const float4*>(soft_stack + (size_t)2 * NN * DD)[fi];
                    v.x = w0 * s0.x + w1 * s1.x + w2 * s2.x;
                    v.y = w0 * s0.y + w1 * s1.y + w2 * s2.y;
                    v.z = w0 * s0.z + w1 * s1.z + w2 * s2.z;
                    v.w = w0 * s0.w + w1 * s1.w + w2 * s2.w;
                } else {
                    v = reinterpret_cast<const float4*>(Ap)[(size_t)gr * 32 + c4];
                }
            }
            int c = c4 * 4;
            AsT[(c + 0) * 64 + r] = v.x;
            AsT[(c + 1) * 64 + r] = v.y;
            AsT[(c + 2) * 64 + r] = v.z;
            AsT[(c + 3) * 64 + r] = v.w;
        }
        __syncthreads();

#pragma unroll 8
        for (int k = 0; k < DD; ++k) {
            ulonglong2 w0 = *reinterpret_cast<const ulonglong2*>(Ws + k * 128 + tx * 4);
            ulonglong2 w1 = *reinterpret_cast<const ulonglong2*>(Ws + k * 128 + 64 + tx * 4);
            float4 av = *reinterpret_cast<const float4*>(AsT + k * 64 + ty * 4);
            ull aa0, aa1, aa2, aa3;
            PACKDUP(aa0, av.x); PACKDUP(aa1, av.y);
            PACKDUP(aa2, av.z); PACKDUP(aa3, av.w);
            FFMA2(acc[0][0], aa0, w0.x); FFMA2(acc[0][1], aa0, w0.y);
            FFMA2(acc[0][2], aa0, w1.x); FFMA2(acc[0][3], aa0, w1.y);
            FFMA2(acc[1][0], aa1, w0.x); FFMA2(acc[1][1], aa1, w0.y);
            FFMA2(acc[1][2], aa1, w1.x); FFMA2(acc[1][3], aa1, w1.y);
            FFMA2(acc[2][0], aa2, w0.x); FFMA2(acc[2][1], aa2, w0.y);
            FFMA2(acc[2][2], aa2, w1.x); FFMA2(acc[2][3], aa2, w1.y);
            FFMA2(acc[3][0], aa3, w0.x); FFMA2(acc[3][1], aa3, w0.y);
            FFMA2(acc[3][2], aa3, w1.x); FFMA2(acc[3][3], aa3, w1.y);
        }
    }
    __syncthreads();   // smem free for epilogue reuse

    // unpack + bias + relu
    float out[4][8];
    float4 b0 = make_float4(0.f, 0.f, 0.f, 0.f), b1 = b0;
    if (bias) {
        b0 = reinterpret_cast<const float4*>(bias)[tx];
        b1 = reinterpret_cast<const float4*>(bias)[16 + tx];
    }
#pragma unroll
    for (int i = 0; i < 4; i++) {
        UNPK(out[i][0], out[i][1], acc[i][0]);
        UNPK(out[i][2], out[i][3], acc[i][1]);
        UNPK(out[i][4], out[i][5], acc[i][2]);
        UNPK(out[i][6], out[i][7], acc[i][3]);
        out[i][0] += b0.x; out[i][1] += b0.y; out[i][2] += b0.z; out[i][3] += b0.w;
        out[i][4] += b1.x; out[i][5] += b1.y; out[i][6] += b1.z; out[i][7] += b1.w;
        if (relu)
#pragma unroll
            for (int j = 0; j < 8; j++) out[i][j] = fmaxf(out[i][j], 0.f);
    }

    if (C) {
#pragma unroll
        for (int i = 0; i < 4; i++) {
            int gr = row0 + ty * 4 + i;
            if (gr >= M) continue;
            float4 lo = make_float4(out[i][0], out[i][1], out[i][2], out[i][3]);
            float4 hi = make_float4(out[i][4], out[i][5], out[i][6], out[i][7]);
            reinterpret_cast<float4*>(C)[(size_t)gr * 32 + tx] = lo;
            reinterpret_cast<float4*>(C)[(size_t)gr * 32 + 16 + tx] = hi;
        }
    }

    if (do_colstat) {
        float* sc = sm;           // 256 floats: [0..127]=sum, [128..255]=sumsq
        sc[tid] = 0.f;
        __syncthreads();
#pragma unroll
        for (int j = 0; j < 8; j++) {
            int col = (j < 4) ? (tx * 4 + j) : (64 + tx * 4 + (j - 4));
            float s = 0.f, q = 0.f;
#pragma unroll
            for (int i = 0; i < 4; i++) {
                int gr = row0 + ty * 4 + i;
                if (gr < M) { float v = out[i][j]; s += v; q += v * v; }
            }
            atomicAdd(&sc[col], s);
            atomicAdd(&sc[128 + col], q);
        }
        __syncthreads();
        if (tid < 128) {
            atomicAdd(&g_colstat[tid], sc[tid]);
            atomicAdd(&g_colstat[128 + tid], sc[128 + tid]);
        }
    }

    if (Qdot) {
        float* sd = sm;           // [64][16]
#pragma unroll
        for (int i = 0; i < 4; i++) {
            int gr = row0 + ty * 4 + i;
            float p = 0.f;
            if (gr < M) {
                float4 q0 = reinterpret_cast<const float4*>(Qdot)[(size_t)gr * 32 + tx];
                float4 q1 = reinterpret_cast<const float4*>(Qdot)[(size_t)gr * 32 + 16 + tx];
                p = out[i][0] * q0.x + out[i][1] * q0.y + out[i][2] * q0.z + out[i][3] * q0.w
                  + out[i][4] * q1.x + out[i][5] * q1.y + out[i][6] * q1.z + out[i][7] * q1.w;
            }
            sd[(ty * 4 + i) * 16 + tx] = p;
        }
        __syncthreads();
        if (tid < 64) {
            float s = 0.f;
#pragma unroll
            for (int j = 0; j < 16; j++) s += sd[tid * 16 + j];
            int gr = row0 + tid;
            if (gr < M) logits[(size_t)gr * BB + bidx] = s;
        }
    }
}

// ---------------- BatchNorm apply (affine computed inline from colstat) ----------------
// mode 0: h = relu(norm(h)) in place.  mode 1: outstack = x + norm(h)
__global__ void bn_apply_kernel(float* __restrict__ h, const float* __restrict__ x,
                                float* __restrict__ outstack, int mode,
                                const float* __restrict__ gamma,
                                const float* __restrict__ beta) {
    int idx = blockIdx.x * blockDim.x + threadIdx.x;
    if (idx >= NN * 32) return;
    int c4 = (idx & 31) * 4;
    const float inv_nn = 1.0f / NN;
    float sc[4], sh[4];
#pragma unroll
    for (int j = 0; j < 4; ++j) {
        int c = c4 + j;
        float mu = g_colstat[c] * inv_nn;
        float var = g_colstat[DD + c] * inv_nn - mu * mu;
        float s = gamma[c] * rsqrtf(var + BN_EPS);
        sc[j] = s;
        sh[j] = beta[c] - mu * s;
    }
    float4 v = reinterpret_cast<float4*>(h)[idx];
    float4 o;
    o.x = v.x * sc[0] + sh[0];
    o.y = v.y * sc[1] + sh[1];
    o.z = v.z * sc[2] + sh[2];
    o.w = v.w * sc[3] + sh[3];
    if (mode == 0) {
        o.x = fmaxf(o.x, 0.f); o.y = fmaxf(o.y, 0.f);
        o.z = fmaxf(o.z, 0.f); o.w = fmaxf(o.w, 0.f);
        reinterpret_cast<float4*>(h)[idx] = o;
    } else {
        float4 xv = reinterpret_cast<const float4*>(x)[idx];
        o.x += xv.x; o.y += xv.y; o.z += xv.z; o.w += xv.w;
        reinterpret_cast<float4*>(outstack)[idx] = o;
    }
}

// ---------------- softmax weights (in place over logits) ----------------
__global__ void softmax_w_kernel(float* __restrict__ logits) {
    int n = blockIdx.x * blockDim.x + threadIdx.x;
    if (n >= NN) return;
    float l0 = logits[(size_t)n * 3 + 0];
    float l1 = logits[(size_t)n * 3 + 1];
    float l2 = logits[(size_t)n * 3 + 2];
    float m = fmaxf(l0, fmaxf(l1, l2));
    float e0 = __expf(l0 - m), e1 = __expf(l1 - m), e2 = __expf(l2 - m);
    float inv = 1.0f / (e0 + e1 + e2);
    logits[(size_t)n * 3 + 0] = e0 * inv;
    logits[(size_t)n * 3 + 1] = e1 * inv;
    logits[(size_t)n * 3 + 2] = e2 * inv;
}

// bc = fuse_b @ refine_W + refine_b
__global__ void bias_combine_kernel(const float* __restrict__ fuse_b,
                                    const float* __restrict__ refine_W,
                                    const float* __restrict__ refine_b) {
    int c = threadIdx.x;
    if (c >= DD) return;
    float s = refine_b[c];
    for (int k = 0; k < DD; ++k) s += fuse_b[k] * refine_W[k * DD + c];
    g_bc[c] = s;
}

// ---------------- host launch ----------------
static inline int gblk(int m) { return (m + 63) / 64; }

extern "C" void kernel_launch(void* const* d_in, const int* in_sizes, int n_in,
                              void* d_out, int out_size) {
    const int*   ei          = (const int*)d_in[0];
    const int*   et          = (const int*)d_in[1];
    const float* item_feats  = (const float*)d_in[2];
    const float* user_emb    = (const float*)d_in[3];
    const float* user_proj_W = (const float*)d_in[4];
    const float* user_proj_b = (const float*)d_in[5];
    const float* item_proj_W = (const float*)d_in[6];
    const float* item_proj_b = (const float*)d_in[7];
    const float* sage_Wl     = (const float*)d_in[8];
    const float* sage_bl     = (const float*)d_in[9];
    const float* sage_Wr     = (const float*)d_in[10];
    const float* bn_gamma    = (const float*)d_in[11];
    const float* bn_beta     = (const float*)d_in[12];
    const float* query_W     = (const float*)d_in[13];
    const float* query_b     = (const float*)d_in[14];
    const float* key_W       = (const float*)d_in[15];
    const float* key_b       = (const float*)d_in[16];
    const float* fuse_W      = (const float*)d_in[17];
    const float* fuse_b      = (const float*)d_in[18];
    const float* refine_W    = (const float*)d_in[19];
    const float* refine_b    = (const float*)d_in[20];
    float* out = (float*)d_out;
    (void)in_sizes; (void)n_in; (void)out_size;

    float *px, *ph, *pagg, *pQ, *pstack, *plog, *pWc, *pbc;
    int* picnt;
    cudaGetSymbolAddress((void**)&px,     g_x);
    cudaGetSymbolAddress((void**)&ph,     g_h);
    cudaGetSymbolAddress((void**)&pagg,   g_agg);
    cudaGetSymbolAddress((void**)&pQ,     g_Q);
    cudaGetSymbolAddress((void**)&pstack, g_stack);
    cudaGetSymbolAddress((void**)&plog,   g_logits);
    cudaGetSymbolAddress((void**)&pWc,    g_Wc);
    cudaGetSymbolAddress((void**)&pbc,    g_bc);
    cudaGetSymbolAddress((void**)&picnt,  g_icnt);

    cudaFuncSetAttribute(gemm_kernel, cudaFuncAttributeMaxDynamicSharedMemorySize, GEMM_SMEM);

    const int NV4 = NN * 32;
    const int APPLY_GRID = (NV4 + 255) / 256;
    const int GATHER_GRID = (NN + 7) / 8;

    // ---- preprocessing + independent GEMMs (user GEMM placed at profile slot 3) ----
    zero_int_kernel<<<256, 256>>>((int4*)picnt, SEGS / 4);              // 0
    count_kernel<<<(EE + 255) / 256, 256>>>(ei, et);                    // 1
    scan1_kernel<<<SCAN_BLOCKS, 1024>>>();                              // 2
    gemm_kernel<<<gblk(NUSER), 256, GEMM_SMEM>>>(user_emb, user_proj_W, // 3 (profiled)
        nullptr, nullptr, user_proj_b, px, NUSER, 0, 0,
        nullptr, nullptr, 0, nullptr, nullptr);
    scan2_kernel<<<1, 512>>>();                                         // 4
    scan3_kernel<<<SCAN_BLOCKS, 1024>>>();                              // 5
    fill_kernel<<<(EE + 255) / 256, 256>>>(ei, et);                     // 6
    gemm_kernel<<<gblk(NITEM), 256, GEMM_SMEM>>>(item_feats, item_proj_W,
        nullptr, nullptr, item_proj_b, px + (size_t)NUSER * DD, NITEM, 0, 0,
        nullptr, nullptr, 0, nullptr, nullptr);

    // precombine fuse+refine (no nonlinearity between them)
    gemm_kernel<<<gblk(DD), 256, GEMM_SMEM>>>(fuse_W, refine_W, nullptr, nullptr,
        nullptr, pWc, DD, 0, 0, nullptr, nullptr, 0, nullptr, nullptr);
    bias_combine_kernel<<<1, 128>>>(fuse_b, refine_W, refine_b);

    for (int b = 0; b < BB; ++b) {
        const float* hin = px;
        for (int l = 0; l < LL; ++l) {
            int bl = b * LL + l;
            gather_kernel<<<GATHER_GRID, 256>>>(hin, pagg, b);   // also zeroes colstat
            // h = agg@Wl + h@Wr + bl  (+ fused BN column stats)
            gemm_kernel<<<gblk(NN), 256, GEMM_SMEM>>>(pagg, sage_Wl + (size_t)bl * DD * DD,
                hin, sage_Wr + (size_t)bl * DD * DD,
                sage_bl + (size_t)bl * DD, ph, NN, 0, 1, nullptr, nullptr, 0, nullptr, nullptr);
            if (l < LL - 1) {
                bn_apply_kernel<<<APPLY_GRID, 256>>>(ph, px, nullptr, 0,
                    bn_gamma + (size_t)bl * DD, bn_beta + (size_t)bl * DD);
            } else {
                bn_apply_kernel<<<APPLY_GRID, 256>>>(ph, px,
                    pstack + (size_t)b * NN * DD, 1,
                    bn_gamma + (size_t)bl * DD, bn_beta + (size_t)bl * DD);
            }
            hin = ph;
        }
    }

    // attention: Q, then K-GEMMs with fused Q-dot (no K materialization)
    gemm_kernel<<<gblk(NN), 256, GEMM_SMEM>>>(px, query_W, nullptr, nullptr,
        query_b, pQ, NN, 0, 0, nullptr, nullptr, 0, nullptr, nullptr);
    for (int b = 0; b < BB; ++b) {
        gemm_kernel<<<gblk(NN), 256, GEMM_SMEM>>>(pstack + (size_t)b * NN * DD,
            key_W + (size_t)b * DD * DD, nullptr, nullptr, key_b + (size_t)b * DD,
            nullptr, NN, 0, 0, pQ, plog, b, nullptr, nullptr);
    }
    // normalize logits -> weights, then final GEMM with fused weighted combine
    softmax_w_kernel<<<(NN + 255) / 256, 256>>>(plog);
    gemm_kernel<<<gblk(NN), 256, GEMM_SMEM>>>(nullptr, pWc, nullptr, nullptr,
        pbc, out, NN, 1, 0, nullptr, nullptr, 0, pstack, plog);
}